// round 1
// baseline (speedup 1.0000x reference)
#include <cuda_runtime.h>
#include <math.h>

#define LSEQ 4096
#define DM   1024
#define NH   16
#define HDIM 64
#define NWIN 8
#define WLEN 512
#define D3   3072

// -------- scratch (allocation-free: device globals) --------
__device__ float g_x1[LSEQ * DM];    // x + rotary (and residual source)
__device__ float g_qkv[LSEQ * D3];   // qkv for current stage
__device__ float g_att[LSEQ * DM];   // attention output (pre out-proj)
__device__ float g_x2[LSEQ * DM];    // after window stage

// ---------------- rotary additive embedding ----------------
__global__ void rotary_kernel(const float* __restrict__ x,
                              const float* __restrict__ rf,
                              float* __restrict__ xo) {
    int idx = blockIdx.x * blockDim.x + threadIdx.x;
    if (idx >= LSEQ * (DM / 2)) return;
    int l = idx / (DM / 2);
    int j = idx % (DM / 2);
    double inv = pow(10000.0, (double)(2 * j) / (double)DM);
    double ang = (double)rf[j] * (double)l / inv;
    float c = (float)cos(ang);
    float s = (float)sin(ang);
    size_t base = (size_t)l * DM;
    xo[base + j]           = x[base + j] + c;
    xo[base + DM / 2 + j]  = x[base + DM / 2 + j] + s;
}

// ---------------- GEMM: C = A @ B^T + bias (+ resid) ----------------
// A: [M, K] row-major (per batch), B: [N, K] row-major (per batch)
// 128x128 tile, BK=16, 256 threads, 8x8 micro-tile per thread.
__global__ __launch_bounds__(256) void gemm_bt_kernel(
    const float* __restrict__ A, const float* __restrict__ B,
    const float* __restrict__ bias, const float* __restrict__ resid,
    float* __restrict__ C, int K, int N,
    long aBatch, long bBatch, long biasBatch, long cBatch)
{
    __shared__ float As[16][132];
    __shared__ float Bs[16][132];
    int tid = threadIdx.x;
    int tx = tid & 15, ty = tid >> 4;

    const float* Ab = A + (size_t)blockIdx.z * aBatch + (size_t)blockIdx.y * 128 * K;
    const float* Bb = B + (size_t)blockIdx.z * bBatch + (size_t)blockIdx.x * 128 * K;

    float acc[8][8];
#pragma unroll
    for (int i = 0; i < 8; i++)
#pragma unroll
        for (int j = 0; j < 8; j++) acc[i][j] = 0.f;

    int mload = tid >> 1;        // 0..127
    int kq    = (tid & 1) * 8;   // 0 or 8

    for (int k0 = 0; k0 < K; k0 += 16) {
        float4 a0 = *(const float4*)&Ab[(size_t)mload * K + k0 + kq];
        float4 a1 = *(const float4*)&Ab[(size_t)mload * K + k0 + kq + 4];
        float4 b0 = *(const float4*)&Bb[(size_t)mload * K + k0 + kq];
        float4 b1 = *(const float4*)&Bb[(size_t)mload * K + k0 + kq + 4];
        __syncthreads();
        As[kq + 0][mload] = a0.x; As[kq + 1][mload] = a0.y;
        As[kq + 2][mload] = a0.z; As[kq + 3][mload] = a0.w;
        As[kq + 4][mload] = a1.x; As[kq + 5][mload] = a1.y;
        As[kq + 6][mload] = a1.z; As[kq + 7][mload] = a1.w;
        Bs[kq + 0][mload] = b0.x; Bs[kq + 1][mload] = b0.y;
        Bs[kq + 2][mload] = b0.z; Bs[kq + 3][mload] = b0.w;
        Bs[kq + 4][mload] = b1.x; Bs[kq + 5][mload] = b1.y;
        Bs[kq + 6][mload] = b1.z; Bs[kq + 7][mload] = b1.w;
        __syncthreads();
#pragma unroll
        for (int k = 0; k < 16; k++) {
            float a[8], b[8];
            *(float4*)&a[0] = *(const float4*)&As[k][ty * 8];
            *(float4*)&a[4] = *(const float4*)&As[k][ty * 8 + 4];
            *(float4*)&b[0] = *(const float4*)&Bs[k][tx * 8];
            *(float4*)&b[4] = *(const float4*)&Bs[k][tx * 8 + 4];
#pragma unroll
            for (int i = 0; i < 8; i++)
#pragma unroll
                for (int j = 0; j < 8; j++)
                    acc[i][j] = fmaf(a[i], b[j], acc[i][j]);
        }
    }

    const float* biasb = bias + (size_t)blockIdx.z * biasBatch + blockIdx.x * 128;
    float bv[8];
    *(float4*)&bv[0] = *(const float4*)&biasb[tx * 8];
    *(float4*)&bv[4] = *(const float4*)&biasb[tx * 8 + 4];

    size_t cbase = (size_t)blockIdx.z * cBatch
                 + ((size_t)blockIdx.y * 128) * N + (size_t)blockIdx.x * 128;
#pragma unroll
    for (int i = 0; i < 8; i++) {
        size_t off = cbase + (size_t)(ty * 8 + i) * N + tx * 8;
        float r[8];
#pragma unroll
        for (int j = 0; j < 8; j++) r[j] = acc[i][j] + bv[j];
        if (resid) {
            float4 r0 = *(const float4*)&resid[off];
            float4 r1 = *(const float4*)&resid[off + 4];
            r[0] += r0.x; r[1] += r0.y; r[2] += r0.z; r[3] += r0.w;
            r[4] += r1.x; r[5] += r1.y; r[6] += r1.z; r[7] += r1.w;
        }
        *(float4*)&C[off]     = make_float4(r[0], r[1], r[2], r[3]);
        *(float4*)&C[off + 4] = make_float4(r[4], r[5], r[6], r[7]);
    }
}

// ---------------- fused flash attention ----------------
// qkv: [LSEQ, 3072] (q | k | v per head in 64-col slices)
// o:   [LSEQ, 1024]
// grid: (segLen/64, NH, nSeg). 256 threads, 4x4 micro-tiles (16x16 grid).
#define FPAD 68
#define FLASH_SMEM (4 * 64 * FPAD * (int)sizeof(float))

__global__ __launch_bounds__(256) void flash_kernel(
    const float* __restrict__ qkv, float* __restrict__ o, int segLen)
{
    extern __shared__ float sm[];
    float* Qs = sm;                 // [64][FPAD]  Qs[d][m]   (pre-scaled)
    float* Ks = sm + 64 * FPAD;     // [64][FPAD]  Ks[d][n]
    float* Vs = sm + 2 * 64 * FPAD; // [64][FPAD]  Vs[t][d]
    float* Ps = sm + 3 * 64 * FPAD; // [64][FPAD]  Ps[kk][m]

    int tid = threadIdx.x;
    int tx = tid & 15, ty = tid >> 4;
    int h = blockIdx.y;
    int segBase = blockIdx.z * segLen;
    int qBase = segBase + blockIdx.x * 64;
    const int ROW = D3;

    // load Q tile (transposed, scaled by HD^-0.5)
    {
        int qcol = h * HDIM;
#pragma unroll
        for (int p = 0; p < 4; p++) {
            int idx = p * 256 + tid;
            int m = idx >> 4;
            int dq = (idx & 15) * 4;
            float4 v = *(const float4*)&qkv[(size_t)(qBase + m) * ROW + qcol + dq];
            Qs[(dq + 0) * FPAD + m] = v.x * 0.125f;
            Qs[(dq + 1) * FPAD + m] = v.y * 0.125f;
            Qs[(dq + 2) * FPAD + m] = v.z * 0.125f;
            Qs[(dq + 3) * FPAD + m] = v.w * 0.125f;
        }
    }

    float oacc[4][4];
#pragma unroll
    for (int i = 0; i < 4; i++)
#pragma unroll
        for (int j = 0; j < 4; j++) oacc[i][j] = 0.f;
    float mrow[4], lrow[4];
#pragma unroll
    for (int i = 0; i < 4; i++) { mrow[i] = -1e30f; lrow[i] = 0.f; }

    int nTiles = segLen / 64;
    int kcol = DM + h * HDIM;
    int vcol = 2 * DM + h * HDIM;

    for (int kt = 0; kt < nTiles; kt++) {
        __syncthreads();  // prior O-gemm done reading Ps/Vs
        int kRow = segBase + kt * 64;
#pragma unroll
        for (int p = 0; p < 4; p++) {
            int idx = p * 256 + tid;
            int n = idx >> 4;
            int dq = (idx & 15) * 4;
            float4 kv = *(const float4*)&qkv[(size_t)(kRow + n) * ROW + kcol + dq];
            Ks[(dq + 0) * FPAD + n] = kv.x;
            Ks[(dq + 1) * FPAD + n] = kv.y;
            Ks[(dq + 2) * FPAD + n] = kv.z;
            Ks[(dq + 3) * FPAD + n] = kv.w;
            float4 vv = *(const float4*)&qkv[(size_t)(kRow + n) * ROW + vcol + dq];
            *(float4*)&Vs[n * FPAD + dq] = vv;
        }
        __syncthreads();

        // S = (Q * scale) @ K^T
        float s[4][4];
#pragma unroll
        for (int i = 0; i < 4; i++)
#pragma unroll
            for (int j = 0; j < 4; j++) s[i][j] = 0.f;
#pragma unroll
        for (int d = 0; d < 64; d++) {
            float4 qa = *(const float4*)&Qs[d * FPAD + ty * 4];
            float4 kb = *(const float4*)&Ks[d * FPAD + tx * 4];
            float qv[4] = {qa.x, qa.y, qa.z, qa.w};
            float kvv[4] = {kb.x, kb.y, kb.z, kb.w};
#pragma unroll
            for (int i = 0; i < 4; i++)
#pragma unroll
                for (int j = 0; j < 4; j++)
                    s[i][j] = fmaf(qv[i], kvv[j], s[i][j]);
        }

        // online softmax per q-row (row group = 16 tx lanes within warp half)
#pragma unroll
        for (int i = 0; i < 4; i++) {
            float rm = fmaxf(fmaxf(s[i][0], s[i][1]), fmaxf(s[i][2], s[i][3]));
#pragma unroll
            for (int off = 1; off < 16; off <<= 1)
                rm = fmaxf(rm, __shfl_xor_sync(0xffffffffu, rm, off));
            float mnew = fmaxf(mrow[i], rm);
            float scale = __expf(mrow[i] - mnew);
            mrow[i] = mnew;
            float rs = 0.f;
#pragma unroll
            for (int j = 0; j < 4; j++) {
                float p = __expf(s[i][j] - mnew);
                s[i][j] = p;
                rs += p;
            }
#pragma unroll
            for (int off = 1; off < 16; off <<= 1)
                rs += __shfl_xor_sync(0xffffffffu, rs, off);
            lrow[i] = lrow[i] * scale + rs;
#pragma unroll
            for (int j = 0; j < 4; j++) oacc[i][j] *= scale;
        }

        // stage P (transposed: Ps[kk][m])
#pragma unroll
        for (int i = 0; i < 4; i++)
#pragma unroll
            for (int j = 0; j < 4; j++)
                Ps[(tx * 4 + j) * FPAD + ty * 4 + i] = s[i][j];
        __syncthreads();

        // O += P @ V
#pragma unroll
        for (int kk = 0; kk < 64; kk++) {
            float4 pa = *(const float4*)&Ps[kk * FPAD + ty * 4];
            float4 vb = *(const float4*)&Vs[kk * FPAD + tx * 4];
            float pv[4] = {pa.x, pa.y, pa.z, pa.w};
            float vv[4] = {vb.x, vb.y, vb.z, vb.w};
#pragma unroll
            for (int i = 0; i < 4; i++)
#pragma unroll
                for (int j = 0; j < 4; j++)
                    oacc[i][j] = fmaf(pv[i], vv[j], oacc[i][j]);
        }
    }

    // epilogue: normalize and store
#pragma unroll
    for (int i = 0; i < 4; i++) {
        float inv = 1.f / lrow[i];
        float4 r = make_float4(oacc[i][0] * inv, oacc[i][1] * inv,
                               oacc[i][2] * inv, oacc[i][3] * inv);
        *(float4*)&o[(size_t)(qBase + ty * 4 + i) * DM + h * HDIM + tx * 4] = r;
    }
}

// ---------------- launcher ----------------
extern "C" void kernel_launch(void* const* d_in, const int* in_sizes, int n_in,
                              void* d_out, int out_size) {
    (void)in_sizes; (void)n_in; (void)out_size;
    const float* x        = (const float*)d_in[0];
    const float* rf       = (const float*)d_in[1];
    const float* w_win_in = (const float*)d_in[2];
    const float* b_win_in = (const float*)d_in[3];
    const float* w_win_out= (const float*)d_in[4];
    const float* b_win_out= (const float*)d_in[5];
    const float* w_fin_in = (const float*)d_in[6];
    const float* b_fin_in = (const float*)d_in[7];
    const float* w_fin_out= (const float*)d_in[8];
    const float* b_fin_out= (const float*)d_in[9];
    float* out = (float*)d_out;

    float *x1, *qkv, *att, *x2;
    cudaGetSymbolAddress((void**)&x1,  g_x1);
    cudaGetSymbolAddress((void**)&qkv, g_qkv);
    cudaGetSymbolAddress((void**)&att, g_att);
    cudaGetSymbolAddress((void**)&x2,  g_x2);

    cudaFuncSetAttribute(flash_kernel,
        cudaFuncAttributeMaxDynamicSharedMemorySize, FLASH_SMEM);

    // 1. rotary
    rotary_kernel<<<(LSEQ * (DM / 2)) / 256, 256>>>(x, rf, x1);

    // 2. window QKV: per window [512,1024] @ [3072,1024]^T
    gemm_bt_kernel<<<dim3(D3 / 128, WLEN / 128, NWIN), 256>>>(
        x1, w_win_in, b_win_in, nullptr, qkv,
        DM, D3,
        (long)WLEN * DM, (long)D3 * DM, (long)D3, (long)WLEN * D3);

    // 3. window attention
    flash_kernel<<<dim3(WLEN / 64, NH, NWIN), 256, FLASH_SMEM>>>(qkv, att, WLEN);

    // 4. window out-proj + residual
    gemm_bt_kernel<<<dim3(DM / 128, WLEN / 128, NWIN), 256>>>(
        att, w_win_out, b_win_out, x1, x2,
        DM, DM,
        (long)WLEN * DM, (long)DM * DM, (long)DM, (long)WLEN * DM);

    // 5. final QKV
    gemm_bt_kernel<<<dim3(D3 / 128, LSEQ / 128, 1), 256>>>(
        x2, w_fin_in, b_fin_in, nullptr, qkv,
        DM, D3, 0, 0, 0, 0);

    // 6. final attention
    flash_kernel<<<dim3(LSEQ / 64, NH, 1), 256, FLASH_SMEM>>>(qkv, att, LSEQ);

    // 7. final out-proj -> d_out
    gemm_bt_kernel<<<dim3(DM / 128, LSEQ / 128, 1), 256>>>(
        att, w_fin_out, b_fin_out, nullptr, out,
        DM, DM, 0, 0, 0, 0);
}

// round 2
// speedup vs baseline: 1.8335x; 1.8335x over previous
#include <cuda_runtime.h>
#include <math.h>
#include <stdint.h>

#define LSEQ 4096
#define DM   1024
#define NH   16
#define HDIM 64
#define NWIN 8
#define WLEN 512
#define D3   3072

// -------- scratch (allocation-free: device globals) --------
__device__ __align__(256) float g_x1[LSEQ * DM];
__device__ __align__(256) float g_qkv[LSEQ * D3];
__device__ __align__(256) float g_att[LSEQ * DM];
__device__ __align__(256) float g_x2[LSEQ * DM];

// ---------------- tf32 mma helpers ----------------
__device__ __forceinline__ void mma_tf32(float c[4], const uint32_t a[4], const uint32_t b[2]) {
    asm volatile(
        "mma.sync.aligned.m16n8k8.row.col.f32.tf32.tf32.f32 "
        "{%0,%1,%2,%3},{%4,%5,%6,%7},{%8,%9},{%0,%1,%2,%3};"
        : "+f"(c[0]), "+f"(c[1]), "+f"(c[2]), "+f"(c[3])
        : "r"(a[0]), "r"(a[1]), "r"(a[2]), "r"(a[3]), "r"(b[0]), "r"(b[1]));
}
__device__ __forceinline__ uint32_t f2tf(float f) {
    uint32_t u;
    asm("cvt.rna.tf32.f32 %0,%1;" : "=r"(u) : "f"(f));
    return u;
}

// cp.async (LDGSTS)
__device__ __forceinline__ void cp16(uint32_t dst, const void* src) {
    asm volatile("cp.async.cg.shared.global [%0],[%1],16;" :: "r"(dst), "l"(src));
}
#define CP_COMMIT() asm volatile("cp.async.commit_group;")
#define CP_WAIT(N)  asm volatile("cp.async.wait_group %0;" :: "n"(N))

// FMA-pipe exp (avoids MUFU floor): e^x via 2^(x*log2e), poly on [-0.5,0.5]
__device__ __forceinline__ float fast_exp(float x) {
    float t = fmaxf(x * 1.4426950408889634f, -126.0f);
    float fi = rintf(t);
    float f = t - fi;
    float p = 1.5403530e-4f;
    p = fmaf(p, f, 1.3333558e-3f);
    p = fmaf(p, f, 9.6181291e-3f);
    p = fmaf(p, f, 5.5504108e-2f);
    p = fmaf(p, f, 2.4022650e-1f);
    p = fmaf(p, f, 6.9314718e-1f);
    p = fmaf(p, f, 1.0f);
    return __int_as_float(__float_as_int(p) + ((int)fi << 23));
}

// ---------------- rotary additive embedding ----------------
__global__ void rotary_kernel(const float* __restrict__ x,
                              const float* __restrict__ rf,
                              float* __restrict__ xo) {
    int idx = blockIdx.x * blockDim.x + threadIdx.x;
    if (idx >= LSEQ * (DM / 2)) return;
    int l = idx / (DM / 2);
    int j = idx % (DM / 2);
    double inv = pow(10000.0, (double)(2 * j) / (double)DM);
    double ang = (double)rf[j] * (double)l / inv;
    float c = (float)cos(ang);
    float s = (float)sin(ang);
    size_t base = (size_t)l * DM;
    xo[base + j]          = x[base + j] + c;
    xo[base + DM / 2 + j] = x[base + DM / 2 + j] + s;
}

// ---------------- tf32 tensor-core GEMM: C = A @ B^T + bias (+resid) ----------------
// A [M,K] rm, B [N,K] rm. Block tile 128x128, BK=32, 8 warps, warp tile 64x32.
#define GPAD 36
#define GEMM_SMEM (4 * 128 * GPAD * (int)sizeof(float))  // A+B double-buffered

__global__ __launch_bounds__(256) void gemm_tc(
    const float* __restrict__ A, const float* __restrict__ B,
    const float* __restrict__ bias, const float* __restrict__ resid,
    float* __restrict__ C, int K, int N,
    long aB, long bB, long biasB, long cB)
{
    extern __shared__ float sm[];
    float* As = sm;                    // [2][128][GPAD]
    float* Bs = sm + 2 * 128 * GPAD;   // [2][128][GPAD]

    int tid = threadIdx.x;
    int lane = tid & 31, wid = tid >> 5;
    int g = lane >> 2, t4 = lane & 3;
    int wm = (wid >> 2) * 64, wn = (wid & 3) * 32;

    const float* Ab = A + (size_t)blockIdx.z * aB + (size_t)blockIdx.y * 128 * K;
    const float* Bb = B + (size_t)blockIdx.z * bB + (size_t)blockIdx.x * 128 * K;

    int lrow = tid >> 1, lk = (tid & 1) * 16;
    uint32_t asBase = (uint32_t)__cvta_generic_to_shared(As);
    uint32_t bsBase = (uint32_t)__cvta_generic_to_shared(Bs);

    float acc[4][4][4];
#pragma unroll
    for (int i = 0; i < 4; i++)
#pragma unroll
        for (int j = 0; j < 4; j++)
#pragma unroll
            for (int k = 0; k < 4; k++) acc[i][j][k] = 0.f;

    auto issue = [&](int buf, int k0) {
        uint32_t ao = asBase + (uint32_t)(buf * 128 * GPAD + lrow * GPAD + lk) * 4u;
        uint32_t bo = bsBase + (uint32_t)(buf * 128 * GPAD + lrow * GPAD + lk) * 4u;
        const float* ag = Ab + (size_t)lrow * K + k0 + lk;
        const float* bg = Bb + (size_t)lrow * K + k0 + lk;
#pragma unroll
        for (int q = 0; q < 4; q++) {
            cp16(ao + q * 16, ag + q * 4);
            cp16(bo + q * 16, bg + q * 4);
        }
    };

    issue(0, 0);
    CP_COMMIT();
    int nk = K >> 5;
    for (int kt = 0; kt < nk; kt++) {
        int cur = kt & 1;
        if (kt + 1 < nk) {
            issue(1 - cur, (kt + 1) * 32);
            CP_COMMIT();
            CP_WAIT(1);
        } else {
            CP_WAIT(0);
        }
        __syncthreads();
        const float* Ac = As + cur * 128 * GPAD;
        const float* Bc = Bs + cur * 128 * GPAD;
#pragma unroll
        for (int c = 0; c < 4; c++) {
            int kc = c * 8;
            uint32_t af[4][4], bf[4][2];
#pragma unroll
            for (int mi = 0; mi < 4; mi++) {
                int r = wm + mi * 16 + g;
                af[mi][0] = f2tf(Ac[r * GPAD + kc + t4]);
                af[mi][1] = f2tf(Ac[(r + 8) * GPAD + kc + t4]);
                af[mi][2] = f2tf(Ac[r * GPAD + kc + t4 + 4]);
                af[mi][3] = f2tf(Ac[(r + 8) * GPAD + kc + t4 + 4]);
            }
#pragma unroll
            for (int ni = 0; ni < 4; ni++) {
                int n = wn + ni * 8 + g;
                bf[ni][0] = f2tf(Bc[n * GPAD + kc + t4]);
                bf[ni][1] = f2tf(Bc[n * GPAD + kc + t4 + 4]);
            }
#pragma unroll
            for (int mi = 0; mi < 4; mi++)
#pragma unroll
                for (int ni = 0; ni < 4; ni++)
                    mma_tf32(acc[mi][ni], af[mi], bf[ni]);
        }
        __syncthreads();
    }

    // epilogue
    const float* bp = bias + (size_t)blockIdx.z * biasB + blockIdx.x * 128;
    size_t cb = (size_t)blockIdx.z * cB + (size_t)(blockIdx.y * 128) * N + blockIdx.x * 128;
#pragma unroll
    for (int mi = 0; mi < 4; mi++) {
#pragma unroll
        for (int ni = 0; ni < 4; ni++) {
            int r0 = wm + mi * 16 + g;
            int c0 = wn + ni * 8 + 2 * t4;
            float b0 = bp[c0], b1 = bp[c0 + 1];
            size_t o0 = cb + (size_t)r0 * N + c0;
            size_t o1 = cb + (size_t)(r0 + 8) * N + c0;
            float2 v0 = make_float2(acc[mi][ni][0] + b0, acc[mi][ni][1] + b1);
            float2 v1 = make_float2(acc[mi][ni][2] + b0, acc[mi][ni][3] + b1);
            if (resid) {
                float2 r0v = *(const float2*)&resid[o0];
                float2 r1v = *(const float2*)&resid[o1];
                v0.x += r0v.x; v0.y += r0v.y;
                v1.x += r1v.x; v1.y += r1v.y;
            }
            *(float2*)&C[o0] = v0;
            *(float2*)&C[o1] = v1;
        }
    }
}

// ---------------- tf32 tensor-core flash attention ----------------
// qkv [LSEQ, 3072] (q|k|v, 64-col head slices). o [LSEQ, 1024].
// Block: 256 thr (8 warps), Q tile 128 rows (16 per warp), K tile 64.
#define FPAD 72
#define FLASH_SMEM ((128 * FPAD + 64 * FPAD + 64 * FPAD) * (int)sizeof(float))

__global__ __launch_bounds__(256) void flash_tc(
    const float* __restrict__ qkv, float* __restrict__ o, int segLen)
{
    extern __shared__ float sm[];
    float* Ps = sm;                 // [128][FPAD]  (also Q staging)
    float* Ks = sm + 128 * FPAD;    // [64][FPAD]   Ks[key][d]
    float* Vs = Ks + 64 * FPAD;     // [64][FPAD]   Vs[t][d]

    int tid = threadIdx.x, lane = tid & 31, wid = tid >> 5;
    int g = lane >> 2, t4 = lane & 3;
    int h = blockIdx.y;
    int segBase = blockIdx.z * segLen;
    int qBase = segBase + blockIdx.x * 128;

    // stage Q (scaled by 1/8) into Ps, then lift fragments to registers
    {
        int r = tid >> 1, half = (tid & 1) * 32;
        const float* src = qkv + (size_t)(qBase + r) * D3 + h * HDIM + half;
        float* dst = Ps + r * FPAD + half;
#pragma unroll
        for (int q = 0; q < 8; q++) {
            float4 v = *(const float4*)(src + q * 4);
            v.x *= 0.125f; v.y *= 0.125f; v.z *= 0.125f; v.w *= 0.125f;
            *(float4*)(dst + q * 4) = v;
        }
    }
    __syncthreads();
    uint32_t qa[8][4];
    {
        int r = wid * 16 + g;
#pragma unroll
        for (int kk = 0; kk < 8; kk++) {
            qa[kk][0] = f2tf(Ps[r * FPAD + kk * 8 + t4]);
            qa[kk][1] = f2tf(Ps[(r + 8) * FPAD + kk * 8 + t4]);
            qa[kk][2] = f2tf(Ps[r * FPAD + kk * 8 + t4 + 4]);
            qa[kk][3] = f2tf(Ps[(r + 8) * FPAD + kk * 8 + t4 + 4]);
        }
    }
    __syncthreads();

    float oa[8][4];
#pragma unroll
    for (int i = 0; i < 8; i++)
#pragma unroll
        for (int j = 0; j < 4; j++) oa[i][j] = 0.f;
    float m0 = -1e30f, m1 = -1e30f, l0 = 0.f, l1 = 0.f;

    int nT = segLen / 64;
    int rr = wid * 16 + g;

    for (int kt = 0; kt < nT; kt++) {
        // load K, V tiles (64 x 64 each)
        {
            int r = tid >> 2, qo = (tid & 3) * 16;
            const float* ks = qkv + (size_t)(segBase + kt * 64 + r) * D3 + DM + h * HDIM + qo;
            const float* vs = qkv + (size_t)(segBase + kt * 64 + r) * D3 + 2 * DM + h * HDIM + qo;
            float* kd = Ks + r * FPAD + qo;
            float* vd = Vs + r * FPAD + qo;
#pragma unroll
            for (int q = 0; q < 4; q++) {
                *(float4*)(kd + q * 4) = *(const float4*)(ks + q * 4);
                *(float4*)(vd + q * 4) = *(const float4*)(vs + q * 4);
            }
        }
        __syncthreads();

        // S = Q @ K^T  (per warp: 16 x 64)
        float s[8][4];
#pragma unroll
        for (int i = 0; i < 8; i++)
#pragma unroll
            for (int j = 0; j < 4; j++) s[i][j] = 0.f;
#pragma unroll
        for (int kk = 0; kk < 8; kk++) {
#pragma unroll
            for (int ni = 0; ni < 8; ni++) {
                uint32_t b[2];
                b[0] = f2tf(Ks[(ni * 8 + g) * FPAD + kk * 8 + t4]);
                b[1] = f2tf(Ks[(ni * 8 + g) * FPAD + kk * 8 + t4 + 4]);
                mma_tf32(s[ni], qa[kk], b);
            }
        }

        // online softmax (rows rr, rr+8; reduce over quad lanes)
        float rm0 = -1e30f, rm1 = -1e30f;
#pragma unroll
        for (int ni = 0; ni < 8; ni++) {
            rm0 = fmaxf(rm0, fmaxf(s[ni][0], s[ni][1]));
            rm1 = fmaxf(rm1, fmaxf(s[ni][2], s[ni][3]));
        }
        rm0 = fmaxf(rm0, __shfl_xor_sync(0xffffffffu, rm0, 1));
        rm0 = fmaxf(rm0, __shfl_xor_sync(0xffffffffu, rm0, 2));
        rm1 = fmaxf(rm1, __shfl_xor_sync(0xffffffffu, rm1, 1));
        rm1 = fmaxf(rm1, __shfl_xor_sync(0xffffffffu, rm1, 2));
        float mn0 = fmaxf(m0, rm0), mn1 = fmaxf(m1, rm1);
        float sc0 = fast_exp(m0 - mn0), sc1 = fast_exp(m1 - mn1);
        m0 = mn0; m1 = mn1;
        float rs0 = 0.f, rs1 = 0.f;
#pragma unroll
        for (int ni = 0; ni < 8; ni++) {
            s[ni][0] = fast_exp(s[ni][0] - mn0);
            s[ni][1] = fast_exp(s[ni][1] - mn0);
            s[ni][2] = fast_exp(s[ni][2] - mn1);
            s[ni][3] = fast_exp(s[ni][3] - mn1);
            rs0 += s[ni][0] + s[ni][1];
            rs1 += s[ni][2] + s[ni][3];
        }
        rs0 += __shfl_xor_sync(0xffffffffu, rs0, 1);
        rs0 += __shfl_xor_sync(0xffffffffu, rs0, 2);
        rs1 += __shfl_xor_sync(0xffffffffu, rs1, 1);
        rs1 += __shfl_xor_sync(0xffffffffu, rs1, 2);
        l0 = l0 * sc0 + rs0;
        l1 = l1 * sc1 + rs1;
#pragma unroll
        for (int ni = 0; ni < 8; ni++) {
            oa[ni][0] *= sc0; oa[ni][1] *= sc0;
            oa[ni][2] *= sc1; oa[ni][3] *= sc1;
        }

        // stage P
#pragma unroll
        for (int ni = 0; ni < 8; ni++) {
            *(float2*)(Ps + rr * FPAD + ni * 8 + 2 * t4)       = make_float2(s[ni][0], s[ni][1]);
            *(float2*)(Ps + (rr + 8) * FPAD + ni * 8 + 2 * t4) = make_float2(s[ni][2], s[ni][3]);
        }
        __syncthreads();

        // O += P @ V
#pragma unroll
        for (int kk = 0; kk < 8; kk++) {
            uint32_t a[4];
            a[0] = f2tf(Ps[rr * FPAD + kk * 8 + t4]);
            a[1] = f2tf(Ps[(rr + 8) * FPAD + kk * 8 + t4]);
            a[2] = f2tf(Ps[rr * FPAD + kk * 8 + t4 + 4]);
            a[3] = f2tf(Ps[(rr + 8) * FPAD + kk * 8 + t4 + 4]);
#pragma unroll
            for (int ni = 0; ni < 8; ni++) {
                uint32_t b[2];
                b[0] = f2tf(Vs[(kk * 8 + t4) * FPAD + ni * 8 + g]);
                b[1] = f2tf(Vs[(kk * 8 + t4 + 4) * FPAD + ni * 8 + g]);
                mma_tf32(oa[ni], a, b);
            }
        }
        __syncthreads();
    }

    // epilogue: normalize and store
    float inv0 = 1.f / l0, inv1 = 1.f / l1;
#pragma unroll
    for (int ni = 0; ni < 8; ni++) {
        float2 v0 = make_float2(oa[ni][0] * inv0, oa[ni][1] * inv0);
        float2 v1 = make_float2(oa[ni][2] * inv1, oa[ni][3] * inv1);
        *(float2*)&o[(size_t)(qBase + rr) * DM + h * HDIM + ni * 8 + 2 * t4]     = v0;
        *(float2*)&o[(size_t)(qBase + rr + 8) * DM + h * HDIM + ni * 8 + 2 * t4] = v1;
    }
}

// ---------------- launcher ----------------
extern "C" void kernel_launch(void* const* d_in, const int* in_sizes, int n_in,
                              void* d_out, int out_size) {
    (void)in_sizes; (void)n_in; (void)out_size;
    const float* x         = (const float*)d_in[0];
    const float* rf        = (const float*)d_in[1];
    const float* w_win_in  = (const float*)d_in[2];
    const float* b_win_in  = (const float*)d_in[3];
    const float* w_win_out = (const float*)d_in[4];
    const float* b_win_out = (const float*)d_in[5];
    const float* w_fin_in  = (const float*)d_in[6];
    const float* b_fin_in  = (const float*)d_in[7];
    const float* w_fin_out = (const float*)d_in[8];
    const float* b_fin_out = (const float*)d_in[9];
    float* out = (float*)d_out;

    float *x1, *qkv, *att, *x2;
    cudaGetSymbolAddress((void**)&x1,  g_x1);
    cudaGetSymbolAddress((void**)&qkv, g_qkv);
    cudaGetSymbolAddress((void**)&att, g_att);
    cudaGetSymbolAddress((void**)&x2,  g_x2);

    cudaFuncSetAttribute(gemm_tc,
        cudaFuncAttributeMaxDynamicSharedMemorySize, GEMM_SMEM);
    cudaFuncSetAttribute(flash_tc,
        cudaFuncAttributeMaxDynamicSharedMemorySize, FLASH_SMEM);

    // 1. rotary
    rotary_kernel<<<(LSEQ * (DM / 2)) / 256, 256>>>(x, rf, x1);

    // 2. window QKV
    gemm_tc<<<dim3(D3 / 128, WLEN / 128, NWIN), 256, GEMM_SMEM>>>(
        x1, w_win_in, b_win_in, nullptr, qkv,
        DM, D3, (long)WLEN * DM, (long)D3 * DM, (long)D3, (long)WLEN * D3);

    // 3. window attention
    flash_tc<<<dim3(WLEN / 128, NH, NWIN), 256, FLASH_SMEM>>>(qkv, att, WLEN);

    // 4. window out-proj + residual
    gemm_tc<<<dim3(DM / 128, WLEN / 128, NWIN), 256, GEMM_SMEM>>>(
        att, w_win_out, b_win_out, x1, x2,
        DM, DM, (long)WLEN * DM, (long)DM * DM, (long)DM, (long)WLEN * DM);

    // 5. final QKV
    gemm_tc<<<dim3(D3 / 128, LSEQ / 128, 1), 256, GEMM_SMEM>>>(
        x2, w_fin_in, b_fin_in, nullptr, qkv,
        DM, D3, 0, 0, 0, 0);

    // 6. final attention
    flash_tc<<<dim3(LSEQ / 128, NH, 1), 256, FLASH_SMEM>>>(qkv, att, LSEQ);

    // 7. final out-proj
    gemm_tc<<<dim3(DM / 128, LSEQ / 128, 1), 256, GEMM_SMEM>>>(
        att, w_fin_out, b_fin_out, nullptr, out,
        DM, DM, 0, 0, 0, 0);
}

// round 3
// speedup vs baseline: 1.9559x; 1.0668x over previous
#include <cuda_runtime.h>
#include <math.h>
#include <stdint.h>

#define LSEQ 4096
#define DM   1024
#define NH   16
#define HDIM 64
#define NWIN 8
#define WLEN 512
#define D3   3072

// -------- scratch (allocation-free: device globals) --------
__device__ __align__(256) float g_x1 [LSEQ * DM];   // rotary out (exact, residual)
__device__ __align__(256) float g_x1t[LSEQ * DM];   // rotary out (tf32-rounded)
__device__ __align__(256) float g_qkv[LSEQ * D3];   // qkv (tf32-rounded)
__device__ __align__(256) float g_att[LSEQ * DM];   // attention out (tf32-rounded)
__device__ __align__(256) float g_x2 [LSEQ * DM];   // window-stage out (tf32-rounded)
// rounded weights: win_w_in | win_w_out | fin_w_in | fin_w_out
#define WT0 0
#define WT1 (NWIN * D3 * DM)                 // 25165824
#define WT2 (WT1 + NWIN * DM * DM)           // 33554432
#define WT3 (WT2 + D3 * DM)                  // 36700160
#define WTN (WT3 + DM * DM)                  // 37748736
__device__ __align__(256) float g_wt[WTN];

// ---------------- tf32 helpers ----------------
__device__ __forceinline__ void mma_tf32(float c[4], const uint32_t a[4], const uint32_t b[2]) {
    asm volatile(
        "mma.sync.aligned.m16n8k8.row.col.f32.tf32.tf32.f32 "
        "{%0,%1,%2,%3},{%4,%5,%6,%7},{%8,%9},{%0,%1,%2,%3};"
        : "+f"(c[0]), "+f"(c[1]), "+f"(c[2]), "+f"(c[3])
        : "r"(a[0]), "r"(a[1]), "r"(a[2]), "r"(a[3]), "r"(b[0]), "r"(b[1]));
}
__device__ __forceinline__ uint32_t f2tf(float f) {
    uint32_t u;
    asm("cvt.rna.tf32.f32 %0,%1;" : "=r"(u) : "f"(f));
    return u;
}
__device__ __forceinline__ float roundtf(float f) { return __uint_as_float(f2tf(f)); }

// cp.async (LDGSTS)
__device__ __forceinline__ void cp16(uint32_t dst, const void* src) {
    asm volatile("cp.async.cg.shared.global [%0],[%1],16;" :: "r"(dst), "l"(src));
}
#define CP_COMMIT() asm volatile("cp.async.commit_group;")
#define CP_WAIT(N)  asm volatile("cp.async.wait_group %0;" :: "n"(N))

// FMA-pipe exp (avoids MUFU floor)
__device__ __forceinline__ float fast_exp(float x) {
    float t = fmaxf(x * 1.4426950408889634f, -126.0f);
    float fi = rintf(t);
    float f = t - fi;
    float p = 1.5403530e-4f;
    p = fmaf(p, f, 1.3333558e-3f);
    p = fmaf(p, f, 9.6181291e-3f);
    p = fmaf(p, f, 5.5504108e-2f);
    p = fmaf(p, f, 2.4022650e-1f);
    p = fmaf(p, f, 6.9314718e-1f);
    p = fmaf(p, f, 1.0f);
    return __int_as_float(__float_as_int(p) + ((int)fi << 23));
}

// ---------------- round-to-tf32 pass ----------------
__global__ void round_tf32_kernel(const float4* __restrict__ s, float4* __restrict__ d, int n4) {
    int i = blockIdx.x * blockDim.x + threadIdx.x;
    if (i >= n4) return;
    float4 v = s[i];
    v.x = roundtf(v.x); v.y = roundtf(v.y);
    v.z = roundtf(v.z); v.w = roundtf(v.w);
    d[i] = v;
}

// ---------------- rotary additive embedding ----------------
__global__ void rotary_kernel(const float* __restrict__ x,
                              const float* __restrict__ rf,
                              float* __restrict__ xo, float* __restrict__ xt) {
    int idx = blockIdx.x * blockDim.x + threadIdx.x;
    if (idx >= LSEQ * (DM / 2)) return;
    int l = idx / (DM / 2);
    int j = idx % (DM / 2);
    double inv = pow(10000.0, (double)(2 * j) / (double)DM);
    double ang = (double)rf[j] * (double)l / inv;
    float c = (float)cos(ang);
    float s = (float)sin(ang);
    size_t base = (size_t)l * DM;
    float v0 = x[base + j] + c;
    float v1 = x[base + DM / 2 + j] + s;
    xo[base + j]          = v0;
    xo[base + DM / 2 + j] = v1;
    xt[base + j]          = roundtf(v0);
    xt[base + DM / 2 + j] = roundtf(v1);
}

// ---------------- tf32 tensor-core GEMM: C = A @ B^T + bias (+resid) ----------------
// Operands are pre-rounded tf32 values: inner loop is pure LDS + MMA.
#define GPAD 36
#define GEMM_SMEM (4 * 128 * GPAD * (int)sizeof(float))

__global__ __launch_bounds__(256) void gemm_tc(
    const float* __restrict__ A, const float* __restrict__ B,
    const float* __restrict__ bias, const float* __restrict__ resid,
    float* __restrict__ C, int K, int N,
    long aB, long bB, long biasB, long cB, int roundOut)
{
    extern __shared__ float sm[];
    float* As = sm;
    float* Bs = sm + 2 * 128 * GPAD;

    int tid = threadIdx.x;
    int lane = tid & 31, wid = tid >> 5;
    int g = lane >> 2, t4 = lane & 3;
    int wm = (wid >> 2) * 64, wn = (wid & 3) * 32;

    const float* Ab = A + (size_t)blockIdx.z * aB + (size_t)blockIdx.y * 128 * K;
    const float* Bb = B + (size_t)blockIdx.z * bB + (size_t)blockIdx.x * 128 * K;

    int lrow = tid >> 1, lk = (tid & 1) * 16;
    uint32_t asBase = (uint32_t)__cvta_generic_to_shared(As);
    uint32_t bsBase = (uint32_t)__cvta_generic_to_shared(Bs);

    float acc[4][4][4];
#pragma unroll
    for (int i = 0; i < 4; i++)
#pragma unroll
        for (int j = 0; j < 4; j++)
#pragma unroll
            for (int k = 0; k < 4; k++) acc[i][j][k] = 0.f;

    auto issue = [&](int buf, int k0) {
        uint32_t ao = asBase + (uint32_t)(buf * 128 * GPAD + lrow * GPAD + lk) * 4u;
        uint32_t bo = bsBase + (uint32_t)(buf * 128 * GPAD + lrow * GPAD + lk) * 4u;
        const float* ag = Ab + (size_t)lrow * K + k0 + lk;
        const float* bg = Bb + (size_t)lrow * K + k0 + lk;
#pragma unroll
        for (int q = 0; q < 4; q++) {
            cp16(ao + q * 16, ag + q * 4);
            cp16(bo + q * 16, bg + q * 4);
        }
    };

    issue(0, 0);
    CP_COMMIT();
    int nk = K >> 5;
    for (int kt = 0; kt < nk; kt++) {
        int cur = kt & 1;
        if (kt + 1 < nk) {
            issue(1 - cur, (kt + 1) * 32);
            CP_COMMIT();
            CP_WAIT(1);
        } else {
            CP_WAIT(0);
        }
        __syncthreads();
        const float* Ac = As + cur * 128 * GPAD;
        const float* Bc = Bs + cur * 128 * GPAD;
#pragma unroll
        for (int c = 0; c < 4; c++) {
            int kc = c * 8;
            uint32_t af[4][4], bf[4][2];
#pragma unroll
            for (int mi = 0; mi < 4; mi++) {
                int r = wm + mi * 16 + g;
                af[mi][0] = __float_as_uint(Ac[r * GPAD + kc + t4]);
                af[mi][1] = __float_as_uint(Ac[(r + 8) * GPAD + kc + t4]);
                af[mi][2] = __float_as_uint(Ac[r * GPAD + kc + t4 + 4]);
                af[mi][3] = __float_as_uint(Ac[(r + 8) * GPAD + kc + t4 + 4]);
            }
#pragma unroll
            for (int ni = 0; ni < 4; ni++) {
                int n = wn + ni * 8 + g;
                bf[ni][0] = __float_as_uint(Bc[n * GPAD + kc + t4]);
                bf[ni][1] = __float_as_uint(Bc[n * GPAD + kc + t4 + 4]);
            }
#pragma unroll
            for (int mi = 0; mi < 4; mi++)
#pragma unroll
                for (int ni = 0; ni < 4; ni++)
                    mma_tf32(acc[mi][ni], af[mi], bf[ni]);
        }
        __syncthreads();
    }

    const float* bp = bias + (size_t)blockIdx.z * biasB + blockIdx.x * 128;
    size_t cb = (size_t)blockIdx.z * cB + (size_t)(blockIdx.y * 128) * N + blockIdx.x * 128;
#pragma unroll
    for (int mi = 0; mi < 4; mi++) {
#pragma unroll
        for (int ni = 0; ni < 4; ni++) {
            int r0 = wm + mi * 16 + g;
            int c0 = wn + ni * 8 + 2 * t4;
            float b0 = bp[c0], b1 = bp[c0 + 1];
            size_t o0 = cb + (size_t)r0 * N + c0;
            size_t o1 = cb + (size_t)(r0 + 8) * N + c0;
            float2 v0 = make_float2(acc[mi][ni][0] + b0, acc[mi][ni][1] + b1);
            float2 v1 = make_float2(acc[mi][ni][2] + b0, acc[mi][ni][3] + b1);
            if (resid) {
                float2 r0v = *(const float2*)&resid[o0];
                float2 r1v = *(const float2*)&resid[o1];
                v0.x += r0v.x; v0.y += r0v.y;
                v1.x += r1v.x; v1.y += r1v.y;
            }
            if (roundOut) {
                v0.x = roundtf(v0.x); v0.y = roundtf(v0.y);
                v1.x = roundtf(v1.x); v1.y = roundtf(v1.y);
            }
            *(float2*)&C[o0] = v0;
            *(float2*)&C[o1] = v1;
        }
    }
}

// ---------------- tf32 tensor-core flash attention ----------------
// qkv values are pre-rounded tf32; inner loops pure LDS + MMA.
#define FPAD 72
#define FLASH_SMEM ((128 * FPAD + 64 * FPAD + 64 * FPAD) * (int)sizeof(float))

__global__ __launch_bounds__(256) void flash_tc(
    const float* __restrict__ qkv, float* __restrict__ o, int segLen)
{
    extern __shared__ float sm[];
    float* Ps = sm;                 // [128][FPAD] (Q staging, then P)
    float* Ks = sm + 128 * FPAD;    // [64][FPAD]
    float* Vs = Ks + 64 * FPAD;     // [64][FPAD]

    int tid = threadIdx.x, lane = tid & 31, wid = tid >> 5;
    int g = lane >> 2, t4 = lane & 3;
    int h = blockIdx.y;
    int segBase = blockIdx.z * segLen;
    int qBase = segBase + blockIdx.x * 128;

    // stage Q (scaled by 1/8 — exact power of two keeps tf32 form)
    {
        int r = tid >> 1, half = (tid & 1) * 32;
        const float* src = qkv + (size_t)(qBase + r) * D3 + h * HDIM + half;
        float* dst = Ps + r * FPAD + half;
#pragma unroll
        for (int q = 0; q < 8; q++) {
            float4 v = *(const float4*)(src + q * 4);
            v.x *= 0.125f; v.y *= 0.125f; v.z *= 0.125f; v.w *= 0.125f;
            *(float4*)(dst + q * 4) = v;
        }
    }
    __syncthreads();
    uint32_t qa[8][4];
    {
        int r = wid * 16 + g;
#pragma unroll
        for (int kk = 0; kk < 8; kk++) {
            qa[kk][0] = __float_as_uint(Ps[r * FPAD + kk * 8 + t4]);
            qa[kk][1] = __float_as_uint(Ps[(r + 8) * FPAD + kk * 8 + t4]);
            qa[kk][2] = __float_as_uint(Ps[r * FPAD + kk * 8 + t4 + 4]);
            qa[kk][3] = __float_as_uint(Ps[(r + 8) * FPAD + kk * 8 + t4 + 4]);
        }
    }
    __syncthreads();

    float oa[8][4];
#pragma unroll
    for (int i = 0; i < 8; i++)
#pragma unroll
        for (int j = 0; j < 4; j++) oa[i][j] = 0.f;
    float m0 = -1e30f, m1 = -1e30f, l0 = 0.f, l1 = 0.f;

    int nT = segLen / 64;
    int rr = wid * 16 + g;

    for (int kt = 0; kt < nT; kt++) {
        {
            int r = tid >> 2, qo = (tid & 3) * 16;
            const float* ks = qkv + (size_t)(segBase + kt * 64 + r) * D3 + DM + h * HDIM + qo;
            const float* vs = qkv + (size_t)(segBase + kt * 64 + r) * D3 + 2 * DM + h * HDIM + qo;
            float* kd = Ks + r * FPAD + qo;
            float* vd = Vs + r * FPAD + qo;
#pragma unroll
            for (int q = 0; q < 4; q++) {
                *(float4*)(kd + q * 4) = *(const float4*)(ks + q * 4);
                *(float4*)(vd + q * 4) = *(const float4*)(vs + q * 4);
            }
        }
        __syncthreads();

        // S = Q @ K^T
        float s[8][4];
#pragma unroll
        for (int i = 0; i < 8; i++)
#pragma unroll
            for (int j = 0; j < 4; j++) s[i][j] = 0.f;
#pragma unroll
        for (int kk = 0; kk < 8; kk++) {
#pragma unroll
            for (int ni = 0; ni < 8; ni++) {
                uint32_t b[2];
                b[0] = __float_as_uint(Ks[(ni * 8 + g) * FPAD + kk * 8 + t4]);
                b[1] = __float_as_uint(Ks[(ni * 8 + g) * FPAD + kk * 8 + t4 + 4]);
                mma_tf32(s[ni], qa[kk], b);
            }
        }

        // online softmax
        float rm0 = -1e30f, rm1 = -1e30f;
#pragma unroll
        for (int ni = 0; ni < 8; ni++) {
            rm0 = fmaxf(rm0, fmaxf(s[ni][0], s[ni][1]));
            rm1 = fmaxf(rm1, fmaxf(s[ni][2], s[ni][3]));
        }
        rm0 = fmaxf(rm0, __shfl_xor_sync(0xffffffffu, rm0, 1));
        rm0 = fmaxf(rm0, __shfl_xor_sync(0xffffffffu, rm0, 2));
        rm1 = fmaxf(rm1, __shfl_xor_sync(0xffffffffu, rm1, 1));
        rm1 = fmaxf(rm1, __shfl_xor_sync(0xffffffffu, rm1, 2));
        float mn0 = fmaxf(m0, rm0), mn1 = fmaxf(m1, rm1);
        float sc0 = fast_exp(m0 - mn0), sc1 = fast_exp(m1 - mn1);
        m0 = mn0; m1 = mn1;
        float rs0 = 0.f, rs1 = 0.f;
#pragma unroll
        for (int ni = 0; ni < 8; ni++) {
            s[ni][0] = fast_exp(s[ni][0] - mn0);
            s[ni][1] = fast_exp(s[ni][1] - mn0);
            s[ni][2] = fast_exp(s[ni][2] - mn1);
            s[ni][3] = fast_exp(s[ni][3] - mn1);
            rs0 += s[ni][0] + s[ni][1];
            rs1 += s[ni][2] + s[ni][3];
        }
        rs0 += __shfl_xor_sync(0xffffffffu, rs0, 1);
        rs0 += __shfl_xor_sync(0xffffffffu, rs0, 2);
        rs1 += __shfl_xor_sync(0xffffffffu, rs1, 1);
        rs1 += __shfl_xor_sync(0xffffffffu, rs1, 2);
        l0 = l0 * sc0 + rs0;
        l1 = l1 * sc1 + rs1;
#pragma unroll
        for (int ni = 0; ni < 8; ni++) {
            oa[ni][0] *= sc0; oa[ni][1] *= sc0;
            oa[ni][2] *= sc1; oa[ni][3] *= sc1;
        }

        // stage P (truncated tf32 via raw bits — P >= 0, error negligible)
#pragma unroll
        for (int ni = 0; ni < 8; ni++) {
            *(float2*)(Ps + rr * FPAD + ni * 8 + 2 * t4)       = make_float2(s[ni][0], s[ni][1]);
            *(float2*)(Ps + (rr + 8) * FPAD + ni * 8 + 2 * t4) = make_float2(s[ni][2], s[ni][3]);
        }
        __syncthreads();

        // O += P @ V
#pragma unroll
        for (int kk = 0; kk < 8; kk++) {
            uint32_t a[4];
            a[0] = __float_as_uint(Ps[rr * FPAD + kk * 8 + t4]);
            a[1] = __float_as_uint(Ps[(rr + 8) * FPAD + kk * 8 + t4]);
            a[2] = __float_as_uint(Ps[rr * FPAD + kk * 8 + t4 + 4]);
            a[3] = __float_as_uint(Ps[(rr + 8) * FPAD + kk * 8 + t4 + 4]);
#pragma unroll
            for (int ni = 0; ni < 8; ni++) {
                uint32_t b[2];
                b[0] = __float_as_uint(Vs[(kk * 8 + t4) * FPAD + ni * 8 + g]);
                b[1] = __float_as_uint(Vs[(kk * 8 + t4 + 4) * FPAD + ni * 8 + g]);
                mma_tf32(oa[ni], a, b);
            }
        }
        __syncthreads();
    }

    // epilogue: normalize, round to tf32 (feeds next GEMM), store
    float inv0 = 1.f / l0, inv1 = 1.f / l1;
#pragma unroll
    for (int ni = 0; ni < 8; ni++) {
        float2 v0 = make_float2(roundtf(oa[ni][0] * inv0), roundtf(oa[ni][1] * inv0));
        float2 v1 = make_float2(roundtf(oa[ni][2] * inv1), roundtf(oa[ni][3] * inv1));
        *(float2*)&o[(size_t)(qBase + rr) * DM + h * HDIM + ni * 8 + 2 * t4]     = v0;
        *(float2*)&o[(size_t)(qBase + rr + 8) * DM + h * HDIM + ni * 8 + 2 * t4] = v1;
    }
}

// ---------------- launcher ----------------
extern "C" void kernel_launch(void* const* d_in, const int* in_sizes, int n_in,
                              void* d_out, int out_size) {
    (void)in_sizes; (void)n_in; (void)out_size;
    const float* x         = (const float*)d_in[0];
    const float* rf        = (const float*)d_in[1];
    const float* w_win_in  = (const float*)d_in[2];
    const float* b_win_in  = (const float*)d_in[3];
    const float* w_win_out = (const float*)d_in[4];
    const float* b_win_out = (const float*)d_in[5];
    const float* w_fin_in  = (const float*)d_in[6];
    const float* b_fin_in  = (const float*)d_in[7];
    const float* w_fin_out = (const float*)d_in[8];
    const float* b_fin_out = (const float*)d_in[9];
    float* out = (float*)d_out;

    float *x1, *x1t, *qkv, *att, *x2, *wt;
    cudaGetSymbolAddress((void**)&x1,  g_x1);
    cudaGetSymbolAddress((void**)&x1t, g_x1t);
    cudaGetSymbolAddress((void**)&qkv, g_qkv);
    cudaGetSymbolAddress((void**)&att, g_att);
    cudaGetSymbolAddress((void**)&x2,  g_x2);
    cudaGetSymbolAddress((void**)&wt,  g_wt);

    cudaFuncSetAttribute(gemm_tc,
        cudaFuncAttributeMaxDynamicSharedMemorySize, GEMM_SMEM);
    cudaFuncSetAttribute(flash_tc,
        cudaFuncAttributeMaxDynamicSharedMemorySize, FLASH_SMEM);

    // 0. pre-round weights to tf32
    round_tf32_kernel<<<(WT1 - WT0) / 1024, 256>>>((const float4*)w_win_in,  (float4*)(wt + WT0), (WT1 - WT0) / 4);
    round_tf32_kernel<<<(WT2 - WT1) / 1024, 256>>>((const float4*)w_win_out, (float4*)(wt + WT1), (WT2 - WT1) / 4);
    round_tf32_kernel<<<(WT3 - WT2) / 1024, 256>>>((const float4*)w_fin_in,  (float4*)(wt + WT2), (WT3 - WT2) / 4);
    round_tf32_kernel<<<(WTN - WT3) / 1024, 256>>>((const float4*)w_fin_out, (float4*)(wt + WT3), (WTN - WT3) / 4);

    // 1. rotary (exact + rounded)
    rotary_kernel<<<(LSEQ * (DM / 2)) / 256, 256>>>(x, rf, x1, x1t);

    // 2. window QKV (out rounded)
    gemm_tc<<<dim3(D3 / 128, WLEN / 128, NWIN), 256, GEMM_SMEM>>>(
        x1t, wt + WT0, b_win_in, nullptr, qkv,
        DM, D3, (long)WLEN * DM, (long)D3 * DM, (long)D3, (long)WLEN * D3, 1);

    // 3. window attention
    flash_tc<<<dim3(WLEN / 128, NH, NWIN), 256, FLASH_SMEM>>>(qkv, att, WLEN);

    // 4. window out-proj + residual (out rounded — feeds GEMM 5)
    gemm_tc<<<dim3(DM / 128, WLEN / 128, NWIN), 256, GEMM_SMEM>>>(
        att, wt + WT1, b_win_out, x1, x2,
        DM, DM, (long)WLEN * DM, (long)DM * DM, (long)DM, (long)WLEN * DM, 1);

    // 5. final QKV (out rounded)
    gemm_tc<<<dim3(D3 / 128, LSEQ / 128, 1), 256, GEMM_SMEM>>>(
        x2, wt + WT2, b_fin_in, nullptr, qkv,
        DM, D3, 0, 0, 0, 0, 1);

    // 6. final attention
    flash_tc<<<dim3(LSEQ / 128, NH, 1), 256, FLASH_SMEM>>>(qkv, att, LSEQ);

    // 7. final out-proj (full precision out)
    gemm_tc<<<dim3(DM / 128, LSEQ / 128, 1), 256, GEMM_SMEM>>>(
        att, wt + WT3, b_fin_out, nullptr, out,
        DM, DM, 0, 0, 0, 0, 0);
}

// round 4
// speedup vs baseline: 2.2542x; 1.1525x over previous
#include <cuda_runtime.h>
#include <math.h>
#include <stdint.h>

#define LSEQ 4096
#define DM   1024
#define NH   16
#define HDIM 64
#define NWIN 8
#define WLEN 512
#define D3   3072

// -------- scratch (allocation-free: device globals) --------
__device__ __align__(256) float g_x1 [LSEQ * DM];   // rotary out (exact, residual)
__device__ __align__(256) float g_x1t[LSEQ * DM];   // rotary out (tf32-rounded)
__device__ __align__(256) float g_qkv[LSEQ * D3];   // qkv (tf32-rounded)
__device__ __align__(256) float g_att[LSEQ * DM];   // attention out (tf32-rounded)
__device__ __align__(256) float g_x2 [LSEQ * DM];   // window-stage out (tf32-rounded)
#define WT0 0
#define WT1 (NWIN * D3 * DM)
#define WT2 (WT1 + NWIN * DM * DM)
#define WT3 (WT2 + D3 * DM)
#define WTN (WT3 + DM * DM)
__device__ __align__(256) float g_wt[WTN];

// ---------------- tf32 / mma helpers ----------------
__device__ __forceinline__ void mma_tf32(float c[4], const uint32_t a[4], const uint32_t b[2]) {
    asm volatile(
        "mma.sync.aligned.m16n8k8.row.col.f32.tf32.tf32.f32 "
        "{%0,%1,%2,%3},{%4,%5,%6,%7},{%8,%9},{%0,%1,%2,%3};"
        : "+f"(c[0]), "+f"(c[1]), "+f"(c[2]), "+f"(c[3])
        : "r"(a[0]), "r"(a[1]), "r"(a[2]), "r"(a[3]), "r"(b[0]), "r"(b[1]));
}
__device__ __forceinline__ uint32_t f2tf(float f) {
    uint32_t u;
    asm("cvt.rna.tf32.f32 %0,%1;" : "=r"(u) : "f"(f));
    return u;
}
__device__ __forceinline__ float roundtf(float f) { return __uint_as_float(f2tf(f)); }

// ldmatrix.x4: four 8x8 b16 tiles == four 8x4 b32 tiles; lane l gets
// tile[l>>2][l&3] (32-bit) — exactly the tf32 mma fragment layout.
__device__ __forceinline__ void ldsm4(uint32_t& r0, uint32_t& r1, uint32_t& r2, uint32_t& r3,
                                      uint32_t addr) {
    asm volatile("ldmatrix.sync.aligned.m8n8.x4.shared.b16 {%0,%1,%2,%3},[%4];"
        : "=r"(r0), "=r"(r1), "=r"(r2), "=r"(r3) : "r"(addr));
}

// cp.async
__device__ __forceinline__ void cp16(uint32_t dst, const void* src) {
    asm volatile("cp.async.cg.shared.global [%0],[%1],16;" :: "r"(dst), "l"(src));
}
#define CP_COMMIT() asm volatile("cp.async.commit_group;")
#define CP_WAIT0()  asm volatile("cp.async.wait_group 0;")

// FMA-pipe 2^t (inputs already in log2 domain)
__device__ __forceinline__ float fast_exp2(float t) {
    t = fmaxf(t, -126.0f);
    float fi = rintf(t);
    float f = t - fi;
    float p = 1.3333558e-3f;
    p = fmaf(p, f, 9.6181291e-3f);
    p = fmaf(p, f, 5.5504108e-2f);
    p = fmaf(p, f, 2.4022650e-1f);
    p = fmaf(p, f, 6.9314718e-1f);
    p = fmaf(p, f, 1.0f);
    return __int_as_float(__float_as_int(p) + ((int)fi << 23));
}

// ---------------- round-to-tf32 pass ----------------
__global__ void round_tf32_kernel(const float4* __restrict__ s, float4* __restrict__ d, int n4) {
    int i = blockIdx.x * blockDim.x + threadIdx.x;
    if (i >= n4) return;
    float4 v = s[i];
    v.x = roundtf(v.x); v.y = roundtf(v.y);
    v.z = roundtf(v.z); v.w = roundtf(v.w);
    d[i] = v;
}

// ---------------- rotary additive embedding ----------------
__global__ void rotary_kernel(const float* __restrict__ x,
                              const float* __restrict__ rf,
                              float* __restrict__ xo, float* __restrict__ xt) {
    int idx = blockIdx.x * blockDim.x + threadIdx.x;
    if (idx >= LSEQ * (DM / 2)) return;
    int l = idx / (DM / 2);
    int j = idx % (DM / 2);
    double inv = pow(10000.0, (double)(2 * j) / (double)DM);
    double ang = (double)rf[j] * (double)l / inv;
    float c = (float)cos(ang);
    float s = (float)sin(ang);
    size_t base = (size_t)l * DM;
    float v0 = x[base + j] + c;
    float v1 = x[base + DM / 2 + j] + s;
    xo[base + j]          = v0;
    xo[base + DM / 2 + j] = v1;
    xt[base + j]          = roundtf(v0);
    xt[base + DM / 2 + j] = roundtf(v1);
}

// ---------------- tf32 tensor-core GEMM: C = A @ B^T + bias (+resid) ----------------
#define GPAD 36
#define GEMM_SMEM (4 * 128 * GPAD * (int)sizeof(float))

__global__ __launch_bounds__(256) void gemm_tc(
    const float* __restrict__ A, const float* __restrict__ B,
    const float* __restrict__ bias, const float* __restrict__ resid,
    float* __restrict__ C, int K, int N,
    long aB, long bB, long biasB, long cB, int roundOut)
{
    extern __shared__ float sm[];
    float* As = sm;                    // [2][128][GPAD]
    float* Bs = sm + 2 * 128 * GPAD;   // [2][128][GPAD]

    int tid = threadIdx.x;
    int lane = tid & 31, wid = tid >> 5;
    int g = lane >> 2, t4 = lane & 3;
    int wm = (wid >> 2) * 64, wn = (wid & 3) * 32;

    const float* Ab = A + (size_t)blockIdx.z * aB + (size_t)blockIdx.y * 128 * K;
    const float* Bb = B + (size_t)blockIdx.z * bB + (size_t)blockIdx.x * 128 * K;

    int lrow = tid >> 1, lk = (tid & 1) * 16;
    uint32_t asBase = (uint32_t)__cvta_generic_to_shared(As);
    uint32_t bsBase = (uint32_t)__cvta_generic_to_shared(Bs);

    // per-lane ldmatrix base addresses
    uint32_t aLm = asBase + (uint32_t)(((wm + (lane & 15)) * GPAD + 4 * (lane >> 4)) * 4);
    uint32_t bLm = bsBase + (uint32_t)(((wn + (lane & 7) + 8 * (lane >> 4)) * GPAD
                                        + 4 * ((lane >> 3) & 1)) * 4);
    const uint32_t bufBytes = 128 * GPAD * 4;

    float acc[4][4][4];
#pragma unroll
    for (int i = 0; i < 4; i++)
#pragma unroll
        for (int j = 0; j < 4; j++)
#pragma unroll
            for (int k = 0; k < 4; k++) acc[i][j][k] = 0.f;

    auto issue = [&](int buf, int k0) {
        uint32_t ao = asBase + (uint32_t)(buf * bufBytes + (lrow * GPAD + lk) * 4);
        uint32_t bo = bsBase + (uint32_t)(buf * bufBytes + (lrow * GPAD + lk) * 4);
        const float* ag = Ab + (size_t)lrow * K + k0 + lk;
        const float* bg = Bb + (size_t)lrow * K + k0 + lk;
#pragma unroll
        for (int q = 0; q < 4; q++) {
            cp16(ao + q * 16, ag + q * 4);
            cp16(bo + q * 16, bg + q * 4);
        }
    };

    issue(0, 0);
    CP_COMMIT();
    int nk = K >> 5;
    for (int kt = 0; kt < nk; kt++) {
        int cur = kt & 1;
        CP_WAIT0();
        __syncthreads();
        if (kt + 1 < nk) {
            issue(1 - cur, (kt + 1) * 32);
            CP_COMMIT();
        }
        uint32_t ab = aLm + cur * bufBytes;
        uint32_t bb = bLm + cur * bufBytes;
#pragma unroll
        for (int c = 0; c < 4; c++) {
            int kc = c * 8;
            uint32_t af[4][4], bf[4][2];
#pragma unroll
            for (int mi = 0; mi < 4; mi++)
                ldsm4(af[mi][0], af[mi][1], af[mi][2], af[mi][3],
                      ab + (uint32_t)((mi * 16 * GPAD + kc) * 4));
            ldsm4(bf[0][0], bf[0][1], bf[1][0], bf[1][1], bb + (uint32_t)(kc * 4));
            ldsm4(bf[2][0], bf[2][1], bf[3][0], bf[3][1],
                  bb + (uint32_t)((16 * GPAD + kc) * 4));
#pragma unroll
            for (int mi = 0; mi < 4; mi++)
#pragma unroll
                for (int ni = 0; ni < 4; ni++)
                    mma_tf32(acc[mi][ni], af[mi], bf[ni]);
        }
    }
    __syncthreads();

    const float* bp = bias + (size_t)blockIdx.z * biasB + blockIdx.x * 128;
    size_t cb = (size_t)blockIdx.z * cB + (size_t)(blockIdx.y * 128) * N + blockIdx.x * 128;
#pragma unroll
    for (int mi = 0; mi < 4; mi++) {
#pragma unroll
        for (int ni = 0; ni < 4; ni++) {
            int r0 = wm + mi * 16 + g;
            int c0 = wn + ni * 8 + 2 * t4;
            float b0 = bp[c0], b1 = bp[c0 + 1];
            size_t o0 = cb + (size_t)r0 * N + c0;
            size_t o1 = cb + (size_t)(r0 + 8) * N + c0;
            float2 v0 = make_float2(acc[mi][ni][0] + b0, acc[mi][ni][1] + b1);
            float2 v1 = make_float2(acc[mi][ni][2] + b0, acc[mi][ni][3] + b1);
            if (resid) {
                float2 r0v = *(const float2*)&resid[o0];
                float2 r1v = *(const float2*)&resid[o1];
                v0.x += r0v.x; v0.y += r0v.y;
                v1.x += r1v.x; v1.y += r1v.y;
            }
            if (roundOut) {
                v0.x = roundtf(v0.x); v0.y = roundtf(v0.y);
                v1.x = roundtf(v1.x); v1.y = roundtf(v1.y);
            }
            *(float2*)&C[o0] = v0;
            *(float2*)&C[o1] = v1;
        }
    }
}

// ---------------- tf32 tensor-core flash attention ----------------
#define KPAD 68
#define VPAD 72
#define FLASH_SMEM ((128 * KPAD + 2 * 64 * KPAD + 2 * 64 * VPAD) * (int)sizeof(float))

__global__ __launch_bounds__(256) void flash_tc(
    const float* __restrict__ qkv, float* __restrict__ o, int segLen)
{
    extern __shared__ float sm[];
    float* Ps = sm;                      // [128][KPAD] (Q staging, then P; warp-private rows)
    float* Ks = sm + 128 * KPAD;         // [2][64][KPAD]
    float* Vs = Ks + 2 * 64 * KPAD;      // [2][64][VPAD]

    int tid = threadIdx.x, lane = tid & 31, wid = tid >> 5;
    int g = lane >> 2, t4 = lane & 3;
    int h = blockIdx.y;
    int segBase = blockIdx.z * segLen;
    int qBase = segBase + blockIdx.x * 128;

    uint32_t psBase = (uint32_t)__cvta_generic_to_shared(Ps);
    uint32_t ksBase = (uint32_t)__cvta_generic_to_shared(Ks);

    // stage Q scaled by 0.125*log2(e) — each warp stages its own 16 rows
    {
        int r = tid >> 1, half = (tid & 1) * 32;
        const float* src = qkv + (size_t)(qBase + r) * D3 + h * HDIM + half;
        float* dst = Ps + r * KPAD + half;
        const float qs = 0.18033688011112042f;  // log2(e)/8
#pragma unroll
        for (int q = 0; q < 8; q++) {
            float4 v = *(const float4*)(src + q * 4);
            v.x *= qs; v.y *= qs; v.z *= qs; v.w *= qs;
            *(float4*)(dst + q * 4) = v;
        }
    }
    __syncwarp();
    uint32_t pLm = psBase + (uint32_t)(((wid * 16 + (lane & 15)) * KPAD + 4 * (lane >> 4)) * 4);
    uint32_t qa[8][4];
#pragma unroll
    for (int kk = 0; kk < 8; kk++)
        ldsm4(qa[kk][0], qa[kk][1], qa[kk][2], qa[kk][3], pLm + (uint32_t)(kk * 8 * 4));
    __syncwarp();

    // K/V cp.async pipeline
    auto issueKV = [&](int buf, int kt) {
        int r = tid >> 2, dq = (tid & 3) * 16;
        const float* ks = qkv + (size_t)(segBase + kt * 64 + r) * D3 + DM + h * HDIM + dq;
        const float* vs = ks + DM;
        uint32_t kd = ksBase + (uint32_t)((buf * 64 * KPAD + r * KPAD + dq) * 4);
        uint32_t vd = ksBase + (uint32_t)((2 * 64 * KPAD + buf * 64 * VPAD + r * VPAD + dq) * 4);
#pragma unroll
        for (int q = 0; q < 4; q++) {
            cp16(kd + q * 16, ks + q * 4);
            cp16(vd + q * 16, vs + q * 4);
        }
    };
    issueKV(0, 0);
    CP_COMMIT();

    float oa[8][4];
#pragma unroll
    for (int i = 0; i < 8; i++)
#pragma unroll
        for (int j = 0; j < 4; j++) oa[i][j] = 0.f;
    float m0 = -1e30f, m1 = -1e30f, l0 = 0.f, l1 = 0.f;

    uint32_t kLm = ksBase + (uint32_t)((((lane & 7) + 8 * (lane >> 4)) * KPAD
                                        + 4 * ((lane >> 3) & 1)) * 4);
    int rr = wid * 16 + g;
    int nT = segLen / 64;

    for (int kt = 0; kt < nT; kt++) {
        int buf = kt & 1;
        CP_WAIT0();
        __syncthreads();
        if (kt + 1 < nT) {
            issueKV(1 - buf, kt + 1);
            CP_COMMIT();
        }

        // S = Q @ K^T  (log2 domain)
        uint32_t kb = kLm + (uint32_t)(buf * 64 * KPAD * 4);
        float s[8][4];
#pragma unroll
        for (int i = 0; i < 8; i++)
#pragma unroll
            for (int j = 0; j < 4; j++) s[i][j] = 0.f;
#pragma unroll
        for (int kk = 0; kk < 8; kk++) {
#pragma unroll
            for (int nip = 0; nip < 4; nip++) {
                uint32_t b0[2], b1[2];
                ldsm4(b0[0], b0[1], b1[0], b1[1],
                      kb + (uint32_t)((nip * 16 * KPAD + kk * 8) * 4));
                mma_tf32(s[2 * nip],     qa[kk], b0);
                mma_tf32(s[2 * nip + 1], qa[kk], b1);
            }
        }

        // online softmax (exp2 domain)
        float rm0 = -1e30f, rm1 = -1e30f;
#pragma unroll
        for (int ni = 0; ni < 8; ni++) {
            rm0 = fmaxf(rm0, fmaxf(s[ni][0], s[ni][1]));
            rm1 = fmaxf(rm1, fmaxf(s[ni][2], s[ni][3]));
        }
        rm0 = fmaxf(rm0, __shfl_xor_sync(0xffffffffu, rm0, 1));
        rm0 = fmaxf(rm0, __shfl_xor_sync(0xffffffffu, rm0, 2));
        rm1 = fmaxf(rm1, __shfl_xor_sync(0xffffffffu, rm1, 1));
        rm1 = fmaxf(rm1, __shfl_xor_sync(0xffffffffu, rm1, 2));
        float mn0 = fmaxf(m0, rm0), mn1 = fmaxf(m1, rm1);
        float sc0 = fast_exp2(m0 - mn0), sc1 = fast_exp2(m1 - mn1);
        m0 = mn0; m1 = mn1;
        float rs0 = 0.f, rs1 = 0.f;
#pragma unroll
        for (int ni = 0; ni < 8; ni++) {
            s[ni][0] = fast_exp2(s[ni][0] - mn0);
            s[ni][1] = fast_exp2(s[ni][1] - mn0);
            s[ni][2] = fast_exp2(s[ni][2] - mn1);
            s[ni][3] = fast_exp2(s[ni][3] - mn1);
            rs0 += s[ni][0] + s[ni][1];
            rs1 += s[ni][2] + s[ni][3];
        }
        rs0 += __shfl_xor_sync(0xffffffffu, rs0, 1);
        rs0 += __shfl_xor_sync(0xffffffffu, rs0, 2);
        rs1 += __shfl_xor_sync(0xffffffffu, rs1, 1);
        rs1 += __shfl_xor_sync(0xffffffffu, rs1, 2);
        l0 = l0 * sc0 + rs0;
        l1 = l1 * sc1 + rs1;
#pragma unroll
        for (int ni = 0; ni < 8; ni++) {
            oa[ni][0] *= sc0; oa[ni][1] *= sc0;
            oa[ni][2] *= sc1; oa[ni][3] *= sc1;
        }

        // stage P (warp-private rows of Ps)
#pragma unroll
        for (int ni = 0; ni < 8; ni++) {
            *(float2*)(Ps + rr * KPAD + ni * 8 + 2 * t4)       = make_float2(s[ni][0], s[ni][1]);
            *(float2*)(Ps + (rr + 8) * KPAD + ni * 8 + 2 * t4) = make_float2(s[ni][2], s[ni][3]);
        }
        __syncwarp();

        // O += P @ V
        const float* Vc = Vs + buf * 64 * VPAD;
#pragma unroll
        for (int kk = 0; kk < 8; kk++) {
            uint32_t a[4];
            ldsm4(a[0], a[1], a[2], a[3], pLm + (uint32_t)(kk * 8 * 4));
#pragma unroll
            for (int ni = 0; ni < 8; ni++) {
                uint32_t b[2];
                b[0] = __float_as_uint(Vc[(kk * 8 + t4) * VPAD + ni * 8 + g]);
                b[1] = __float_as_uint(Vc[(kk * 8 + t4 + 4) * VPAD + ni * 8 + g]);
                mma_tf32(oa[ni], a, b);
            }
        }
    }

    // epilogue: normalize, round to tf32, store
    float inv0 = 1.f / l0, inv1 = 1.f / l1;
#pragma unroll
    for (int ni = 0; ni < 8; ni++) {
        float2 v0 = make_float2(roundtf(oa[ni][0] * inv0), roundtf(oa[ni][1] * inv0));
        float2 v1 = make_float2(roundtf(oa[ni][2] * inv1), roundtf(oa[ni][3] * inv1));
        *(float2*)&o[(size_t)(qBase + rr) * DM + h * HDIM + ni * 8 + 2 * t4]     = v0;
        *(float2*)&o[(size_t)(qBase + rr + 8) * DM + h * HDIM + ni * 8 + 2 * t4] = v1;
    }
}

// ---------------- launcher ----------------
extern "C" void kernel_launch(void* const* d_in, const int* in_sizes, int n_in,
                              void* d_out, int out_size) {
    (void)in_sizes; (void)n_in; (void)out_size;
    const float* x         = (const float*)d_in[0];
    const float* rf        = (const float*)d_in[1];
    const float* w_win_in  = (const float*)d_in[2];
    const float* b_win_in  = (const float*)d_in[3];
    const float* w_win_out = (const float*)d_in[4];
    const float* b_win_out = (const float*)d_in[5];
    const float* w_fin_in  = (const float*)d_in[6];
    const float* b_fin_in  = (const float*)d_in[7];
    const float* w_fin_out = (const float*)d_in[8];
    const float* b_fin_out = (const float*)d_in[9];
    float* out = (float*)d_out;

    float *x1, *x1t, *qkv, *att, *x2, *wt;
    cudaGetSymbolAddress((void**)&x1,  g_x1);
    cudaGetSymbolAddress((void**)&x1t, g_x1t);
    cudaGetSymbolAddress((void**)&qkv, g_qkv);
    cudaGetSymbolAddress((void**)&att, g_att);
    cudaGetSymbolAddress((void**)&x2,  g_x2);
    cudaGetSymbolAddress((void**)&wt,  g_wt);

    cudaFuncSetAttribute(gemm_tc,
        cudaFuncAttributeMaxDynamicSharedMemorySize, GEMM_SMEM);
    cudaFuncSetAttribute(flash_tc,
        cudaFuncAttributeMaxDynamicSharedMemorySize, FLASH_SMEM);

    // 0. pre-round weights
    round_tf32_kernel<<<(WT1 - WT0) / 1024, 256>>>((const float4*)w_win_in,  (float4*)(wt + WT0), (WT1 - WT0) / 4);
    round_tf32_kernel<<<(WT2 - WT1) / 1024, 256>>>((const float4*)w_win_out, (float4*)(wt + WT1), (WT2 - WT1) / 4);
    round_tf32_kernel<<<(WT3 - WT2) / 1024, 256>>>((const float4*)w_fin_in,  (float4*)(wt + WT2), (WT3 - WT2) / 4);
    round_tf32_kernel<<<(WTN - WT3) / 1024, 256>>>((const float4*)w_fin_out, (float4*)(wt + WT3), (WTN - WT3) / 4);

    // 1. rotary
    rotary_kernel<<<(LSEQ * (DM / 2)) / 256, 256>>>(x, rf, x1, x1t);

    // 2. window QKV
    gemm_tc<<<dim3(D3 / 128, WLEN / 128, NWIN), 256, GEMM_SMEM>>>(
        x1t, wt + WT0, b_win_in, nullptr, qkv,
        DM, D3, (long)WLEN * DM, (long)D3 * DM, (long)D3, (long)WLEN * D3, 1);

    // 3. window attention
    flash_tc<<<dim3(WLEN / 128, NH, NWIN), 256, FLASH_SMEM>>>(qkv, att, WLEN);

    // 4. window out-proj + residual
    gemm_tc<<<dim3(DM / 128, WLEN / 128, NWIN), 256, GEMM_SMEM>>>(
        att, wt + WT1, b_win_out, x1, x2,
        DM, DM, (long)WLEN * DM, (long)DM * DM, (long)DM, (long)WLEN * DM, 1);

    // 5. final QKV
    gemm_tc<<<dim3(D3 / 128, LSEQ / 128, 1), 256, GEMM_SMEM>>>(
        x2, wt + WT2, b_fin_in, nullptr, qkv,
        DM, D3, 0, 0, 0, 0, 1);

    // 6. final attention
    flash_tc<<<dim3(LSEQ / 128, NH, 1), 256, FLASH_SMEM>>>(qkv, att, LSEQ);

    // 7. final out-proj
    gemm_tc<<<dim3(DM / 128, LSEQ / 128, 1), 256, GEMM_SMEM>>>(
        att, wt + WT3, b_fin_out, nullptr, out,
        DM, DM, 0, 0, 0, 0, 0);
}